// round 16
// baseline (speedup 1.0000x reference)
#include <cuda_runtime.h>
#include <cuda_bf16.h>
#include <math.h>

// Problem shape (fixed by setup_inputs): N=50000, E=800000, D=256
#define DIM 256
#define MAXN 50000
#define MAXE 800000

// Parallel scan config
#define SCAN_CHUNK 512
#define NUM_SCAN_BLOCKS ((MAXN + SCAN_CHUNK - 1) / SCAN_CHUNK)   // 98

// Scratch (static __device__ globals — no runtime allocation allowed)
__device__ int   g_is64;
__device__ int   g_cnt[MAXN];
__device__ int   g_start[MAXN + 1];
__device__ int   g_cursor[MAXN];
__device__ int   g_esrc[MAXE];
__device__ float g_dinv[MAXN];
__device__ __nv_bfloat16 g_hb[(size_t)MAXN * DIM];   // h = x @ W in bf16
__device__ float g_colsum[DIM];
__device__ int   g_blocksum[NUM_SCAN_BLOCKS];
__device__ int   g_blockbase[NUM_SCAN_BLOCKS];

// ---------------------------------------------------------------------------
// k_detect: int64 vs int32 edge buffer (odd 32-bit words all zero => int64)
// ---------------------------------------------------------------------------
__global__ void k_detect(const int* __restrict__ p32, int nwords) {
    __shared__ int any_nonzero;
    if (threadIdx.x == 0) any_nonzero = 0;
    __syncthreads();
    int idx = 1 + 2 * threadIdx.x;
    if (idx < nwords && p32[idx] != 0) atomicOr(&any_nonzero, 1);
    __syncthreads();
    if (threadIdx.x == 0) g_is64 = any_nonzero ? 0 : 1;
}

__device__ __forceinline__ int load_idx(const int* p32, long long pos,
                                        int stride, int N) {
    int v = p32[pos * stride];
    return min(max(v, 0), N - 1);   // clamp: garbage must never reach an atomic
}

// ---------------------------------------------------------------------------
__global__ void k_init(int N) {
    int i = blockIdx.x * blockDim.x + threadIdx.x;
    if (i < N)   g_cnt[i] = 0;
    if (i < DIM) g_colsum[i] = 0.0f;
}

// ---------------------------------------------------------------------------
__global__ void k_hist(const int* __restrict__ p32, int E, int N) {
    int e = blockIdx.x * blockDim.x + threadIdx.x;
    if (e < E) {
        int stride = 1 + g_is64;
        int c = load_idx(p32, (long long)E + e, stride, N);
        atomicAdd(&g_cnt[c], 1);
    }
}

// ---------------------------------------------------------------------------
// 3-phase parallel scan (validated: 110us serial -> ~8us)
// ---------------------------------------------------------------------------
__global__ void k_scan1(int N) {
    __shared__ int wsum[8];
    const int b = blockIdx.x, t = threadIdx.x;
    const int i0 = b * SCAN_CHUNK + 2 * t;
    const int i1 = i0 + 1;
    int e0 = (i0 < N) ? g_cnt[i0] : 0;
    int e1 = (i1 < N) ? g_cnt[i1] : 0;
    int s = e0 + e1;
#pragma unroll
    for (int o = 16; o > 0; o >>= 1) s += __shfl_down_sync(0xffffffffu, s, o);
    if ((t & 31) == 0) wsum[t >> 5] = s;
    __syncthreads();
    if (t < 8) {
        int v = wsum[t];
#pragma unroll
        for (int o = 4; o > 0; o >>= 1) v += __shfl_down_sync(0xffu, v, o);
        if (t == 0) g_blocksum[b] = v;
    }
}

__global__ void k_scan2() {
    __shared__ int sh[128];
    const int t = threadIdx.x;
    int v = (t < NUM_SCAN_BLOCKS) ? g_blocksum[t] : 0;
    sh[t] = v;
    __syncthreads();
    for (int o = 1; o < 128; o <<= 1) {
        int u = (t >= o) ? sh[t - o] : 0;
        __syncthreads();
        sh[t] += u;
        __syncthreads();
    }
    if (t < NUM_SCAN_BLOCKS) g_blockbase[t] = sh[t] - v;  // exclusive
}

__global__ void k_scan3(int N) {
    __shared__ int warp_inc[8];
    const int b = blockIdx.x, t = threadIdx.x;
    const int lane = t & 31, wid = t >> 5;
    const int i0 = b * SCAN_CHUNK + 2 * t;
    const int i1 = i0 + 1;
    int e0 = (i0 < N) ? g_cnt[i0] : 0;
    int e1 = (i1 < N) ? g_cnt[i1] : 0;
    int s = e0 + e1;

    int v = s;
#pragma unroll
    for (int o = 1; o < 32; o <<= 1) {
        int u = __shfl_up_sync(0xffffffffu, v, o);
        if (lane >= o) v += u;
    }
    if (lane == 31) warp_inc[wid] = v;
    __syncthreads();
    if (t < 8) {
        int w = warp_inc[t];
#pragma unroll
        for (int o = 1; o < 8; o <<= 1) {
            int u = __shfl_up_sync(0xffu, w, o);
            if (t >= o) w += u;
        }
        warp_inc[t] = w;
    }
    __syncthreads();

    int base = g_blockbase[b] + (wid > 0 ? warp_inc[wid - 1] : 0) + (v - s);
    if (i0 < N) {
        g_start[i0]  = base;
        g_cursor[i0] = base;
        g_dinv[i0]   = rsqrtf((float)(e0 + 1));
        if (i0 == N - 1) g_start[N] = base + e0;
    }
    if (i1 < N) {
        int b1 = base + e0;
        g_start[i1]  = b1;
        g_cursor[i1] = b1;
        g_dinv[i1]   = rsqrtf((float)(e1 + 1));
        if (i1 == N - 1) g_start[N] = b1 + e1;
    }
}

// ---------------------------------------------------------------------------
__global__ void k_place(const int* __restrict__ p32, int E, int N) {
    int e = blockIdx.x * blockDim.x + threadIdx.x;
    if (e < E) {
        int stride = 1 + g_is64;
        int r = load_idx(p32, (long long)e, stride, N);
        int c = load_idx(p32, (long long)E + e, stride, N);
        int pos = atomicAdd(&g_cursor[c], 1);
        if (pos < MAXE) g_esrc[pos] = r;
    }
}

// ---------------------------------------------------------------------------
// k_gemm: h = x @ W via tf32 mma.sync m16n8k8, output stored as bf16.
// Block tile 128x64, BK=32, 8 warps as 4(M)x2(N), warp tile 32x32 = 2x4 mmas.
// ---------------------------------------------------------------------------
#define BM 128
#define BN 64
#define BK 32

__device__ __forceinline__ unsigned f2tf32(float f) {
    unsigned r;
    asm("cvt.rna.tf32.f32 %0, %1;" : "=r"(r) : "f"(f));
    return r;
}

__device__ __forceinline__ void mma_tf32(float* d, const unsigned* a,
                                         const unsigned* b) {
    asm volatile(
        "mma.sync.aligned.m16n8k8.row.col.f32.tf32.tf32.f32 "
        "{%0,%1,%2,%3}, {%4,%5,%6,%7}, {%8,%9}, {%0,%1,%2,%3};"
        : "+f"(d[0]), "+f"(d[1]), "+f"(d[2]), "+f"(d[3])
        : "r"(a[0]), "r"(a[1]), "r"(a[2]), "r"(a[3]), "r"(b[0]), "r"(b[1]));
}

__global__ void k_gemm(const float* __restrict__ x,
                       const float* __restrict__ W, int N) {
    __shared__ float xs[BM][36];   // 128x32, row stride 36 (4g+t bijective)
    __shared__ float ws[BK][72];   // 32x64, row stride 72 (8t+g bijective)

    const int tid  = threadIdx.x;
    const int warp = tid >> 5;
    const int lane = tid & 31;
    const int g    = lane >> 2;
    const int t4   = lane & 3;

    const int rowBase = blockIdx.x * BM;
    const int colBase = blockIdx.y * BN;
    const int wm = (warp >> 1) * 32;
    const int wn = (warp & 1) * 32;

    float acc[2][4][4];
#pragma unroll
    for (int m = 0; m < 2; m++)
#pragma unroll
        for (int n = 0; n < 4; n++)
#pragma unroll
            for (int r = 0; r < 4; r++) acc[m][n][r] = 0.0f;

    for (int kc = 0; kc < DIM; kc += BK) {
#pragma unroll
        for (int l = 0; l < 4; l++) {
            int idx = tid + l * 256;
            int r = idx >> 3, c4 = idx & 7;
            int gr = rowBase + r;
            float4 v = (gr < N)
                ? *(const float4*)&x[(size_t)gr * DIM + kc + c4 * 4]
                : make_float4(0.f, 0.f, 0.f, 0.f);
            *(float4*)&xs[r][c4 * 4] = v;
        }
#pragma unroll
        for (int l = 0; l < 2; l++) {
            int idx = tid + l * 256;
            int r = idx >> 4, c4 = idx & 15;
            float4 v = *(const float4*)&W[(size_t)(kc + r) * DIM + colBase + c4 * 4];
            *(float4*)&ws[r][c4 * 4] = v;
        }
        __syncthreads();

#pragma unroll
        for (int ks = 0; ks < BK; ks += 8) {
            unsigned A[2][4], B[4][2];
#pragma unroll
            for (int m = 0; m < 2; m++) {
                int r0 = wm + m * 16 + g;
                A[m][0] = f2tf32(xs[r0][ks + t4]);
                A[m][1] = f2tf32(xs[r0 + 8][ks + t4]);
                A[m][2] = f2tf32(xs[r0][ks + t4 + 4]);
                A[m][3] = f2tf32(xs[r0 + 8][ks + t4 + 4]);
            }
#pragma unroll
            for (int n = 0; n < 4; n++) {
                int c = wn + n * 8 + g;
                B[n][0] = f2tf32(ws[ks + t4][c]);
                B[n][1] = f2tf32(ws[ks + t4 + 4][c]);
            }
#pragma unroll
            for (int m = 0; m < 2; m++)
#pragma unroll
                for (int n = 0; n < 4; n++) mma_tf32(acc[m][n], A[m], B[n]);
        }
        __syncthreads();
    }

    // store as bf16: c0,c1 at (g, 2t4),(g, 2t4+1); c2,c3 at row g+8
#pragma unroll
    for (int m = 0; m < 2; m++) {
        int r0 = rowBase + wm + m * 16 + g;
        int r1 = r0 + 8;
#pragma unroll
        for (int n = 0; n < 4; n++) {
            int c = colBase + wn + n * 8 + 2 * t4;
            if (r0 < N)
                *(__nv_bfloat162*)&g_hb[(size_t)r0 * DIM + c] =
                    __floats2bfloat162_rn(acc[m][n][0], acc[m][n][1]);
            if (r1 < N)
                *(__nv_bfloat162*)&g_hb[(size_t)r1 * DIM + c] =
                    __floats2bfloat162_rn(acc[m][n][2], acc[m][n][3]);
        }
    }
}

// ---------------------------------------------------------------------------
// k_gather: fused aggregate + bias + sigmoid + column-sum. Warp per node.
// bf16 h: lane owns 8 contiguous cols = ONE uint4 (LDG.128) per edge row.
// Accumulation in fp32.
// ---------------------------------------------------------------------------
#define GATHER_BLOCKS 1184
__device__ __forceinline__ float sigmoidf(float v) {
    return 1.0f / (1.0f + expf(-v));
}

// unpack uint4 (8 bf16) -> 8 floats
__device__ __forceinline__ void unpack8(const uint4& u, float* f) {
    float2 p;
    p = __bfloat1622float2(*(const __nv_bfloat162*)&u.x); f[0] = p.x; f[1] = p.y;
    p = __bfloat1622float2(*(const __nv_bfloat162*)&u.y); f[2] = p.x; f[3] = p.y;
    p = __bfloat1622float2(*(const __nv_bfloat162*)&u.z); f[4] = p.x; f[5] = p.y;
    p = __bfloat1622float2(*(const __nv_bfloat162*)&u.w); f[6] = p.x; f[7] = p.y;
}

__global__ void k_gather(const float* __restrict__ b_conv, int N) {
    const int lane = threadIdx.x & 31;
    const int wid  = threadIdx.x >> 5;
    const int gw   = blockIdx.x * 8 + wid;
    const int nwarps = gridDim.x * 8;
    const int d0 = lane * 8;             // 8 contiguous columns per lane

    const uint4* __restrict__ hb4 = (const uint4*)g_hb;  // 8 bf16 per uint4
    const int rowStride = DIM / 8;       // 32 uint4 per row
    const int laneOff = d0 / 8;          // = lane

    float bc[8];
#pragma unroll
    for (int j = 0; j < 8; j++) bc[j] = b_conv[d0 + j];

    float cs[8];
#pragma unroll
    for (int j = 0; j < 8; j++) cs[j] = 0.0f;

    for (int n = gw; n < N; n += nwarps) {
        const float dn = g_dinv[n];
        const int base = g_start[n];
        const int end  = g_start[n + 1];

        float a[8];
        {   // self-loop: norm = dinv[n]^2
            const float wn = dn * dn;
            float hv[8];
            unpack8(hb4[(size_t)n * rowStride + laneOff], hv);
#pragma unroll
            for (int j = 0; j < 8; j++) a[j] = hv[j] * wn;
        }

        int i = base;
        for (; i + 2 <= end; i += 2) {
            int ra = g_esrc[i];
            int rb = g_esrc[i + 1];
            float wa = g_dinv[ra] * dn;
            float wb = g_dinv[rb] * dn;
            uint4 ua = hb4[(size_t)ra * rowStride + laneOff];
            uint4 ub = hb4[(size_t)rb * rowStride + laneOff];
            float va[8], vb[8];
            unpack8(ua, va);
            unpack8(ub, vb);
#pragma unroll
            for (int j = 0; j < 8; j++) a[j] = fmaf(va[j], wa, a[j]);
#pragma unroll
            for (int j = 0; j < 8; j++) a[j] = fmaf(vb[j], wb, a[j]);
        }
        if (i < end) {
            int   r  = g_esrc[i];
            float we = g_dinv[r] * dn;
            float v[8];
            unpack8(hb4[(size_t)r * rowStride + laneOff], v);
#pragma unroll
            for (int j = 0; j < 8; j++) a[j] = fmaf(v[j], we, a[j]);
        }

#pragma unroll
        for (int j = 0; j < 8; j++) cs[j] += sigmoidf(a[j] + bc[j]);
    }

    // block-level reduction: smem atomics, then one global atomic per column
    __shared__ float scol[DIM];
    scol[threadIdx.x] = 0.0f;
    __syncthreads();
#pragma unroll
    for (int j = 0; j < 8; j++) atomicAdd(&scol[d0 + j], cs[j]);
    __syncthreads();
    atomicAdd(&g_colsum[threadIdx.x], scol[threadIdx.x]);
}

// ---------------------------------------------------------------------------
__global__ void k_final(const float* __restrict__ w_lin,
                        const float* __restrict__ b_lin,
                        float* __restrict__ out, int N) {
    __shared__ float red[DIM];
    int d = threadIdx.x;
    red[d] = g_colsum[d] * (1.0f / (float)N) * w_lin[d];
    __syncthreads();
    for (int s = 128; s > 0; s >>= 1) {
        if (d < s) red[d] += red[d + s];
        __syncthreads();
    }
    if (d == 0) {
        float z = red[0] + b_lin[0];
        out[0] = 1.0f / (1.0f + expf(-z));
    }
}

// ---------------------------------------------------------------------------
extern "C" void kernel_launch(void* const* d_in, const int* in_sizes, int n_in,
                              void* d_out, int out_size) {
    const float* x      = (const float*)d_in[0];
    const int*   e32    = (const int*)d_in[1];
    const float* W      = (const float*)d_in[2];
    const float* b_conv = (const float*)d_in[3];
    const float* w_lin  = (const float*)d_in[4];
    const float* b_lin  = (const float*)d_in[5];
    float*       out    = (float*)d_out;

    int N = in_sizes[0] / DIM;
    int E = in_sizes[1] / 2;

    k_detect<<<1, 256>>>(e32, 2 * E);
    k_init<<<(N + 255) / 256, 256>>>(N);
    k_hist<<<(E + 255) / 256, 256>>>(e32, E, N);

    k_scan1<<<NUM_SCAN_BLOCKS, 256>>>(N);
    k_scan2<<<1, 128>>>();
    k_scan3<<<NUM_SCAN_BLOCKS, 256>>>(N);

    k_place<<<(E + 255) / 256, 256>>>(e32, E, N);
    {
        dim3 grid((N + BM - 1) / BM, DIM / BN);
        k_gemm<<<grid, 256>>>(x, W, N);
    }
    k_gather<<<GATHER_BLOCKS, 256>>>(b_conv, N);
    k_final<<<1, 256>>>(w_lin, b_lin, out, N);
}

// round 17
// speedup vs baseline: 1.4340x; 1.4340x over previous
#include <cuda_runtime.h>
#include <cuda_bf16.h>
#include <math.h>

// Problem shape (fixed by setup_inputs): N=50000, E=800000, D=256
#define DIM 256
#define MAXN 50000
#define MAXE 800000

// Parallel scan config
#define SCAN_CHUNK 512
#define NUM_SCAN_BLOCKS ((MAXN + SCAN_CHUNK - 1) / SCAN_CHUNK)   // 98

// Scratch (static __device__ globals — no runtime allocation allowed)
__device__ int   g_is64;
__device__ int   g_cnt[MAXN];
__device__ int   g_start[MAXN + 1];
__device__ int   g_cursor[MAXN];
__device__ int   g_esrc[MAXE];
__device__ float g_dinv[MAXN];
__device__ __nv_bfloat16 g_hb[(size_t)MAXN * DIM];   // h = x @ W in bf16
__device__ float g_colsum[DIM];
__device__ int   g_blocksum[NUM_SCAN_BLOCKS];
__device__ int   g_blockbase[NUM_SCAN_BLOCKS];

// ---------------------------------------------------------------------------
// k_detect: int64 vs int32 edge buffer (odd 32-bit words all zero => int64)
// ---------------------------------------------------------------------------
__global__ void k_detect(const int* __restrict__ p32, int nwords) {
    __shared__ int any_nonzero;
    if (threadIdx.x == 0) any_nonzero = 0;
    __syncthreads();
    int idx = 1 + 2 * threadIdx.x;
    if (idx < nwords && p32[idx] != 0) atomicOr(&any_nonzero, 1);
    __syncthreads();
    if (threadIdx.x == 0) g_is64 = any_nonzero ? 0 : 1;
}

__device__ __forceinline__ int load_idx(const int* p32, long long pos,
                                        int stride, int N) {
    int v = p32[pos * stride];
    return min(max(v, 0), N - 1);   // clamp: garbage must never reach an atomic
}

// ---------------------------------------------------------------------------
__global__ void k_init(int N) {
    int i = blockIdx.x * blockDim.x + threadIdx.x;
    if (i < N)   g_cnt[i] = 0;
    if (i < DIM) g_colsum[i] = 0.0f;
}

// ---------------------------------------------------------------------------
__global__ void k_hist(const int* __restrict__ p32, int E, int N) {
    int e = blockIdx.x * blockDim.x + threadIdx.x;
    if (e < E) {
        int stride = 1 + g_is64;
        int c = load_idx(p32, (long long)E + e, stride, N);
        atomicAdd(&g_cnt[c], 1);
    }
}

// ---------------------------------------------------------------------------
// 3-phase parallel scan (validated)
// ---------------------------------------------------------------------------
__global__ void k_scan1(int N) {
    __shared__ int wsum[8];
    const int b = blockIdx.x, t = threadIdx.x;
    const int i0 = b * SCAN_CHUNK + 2 * t;
    const int i1 = i0 + 1;
    int e0 = (i0 < N) ? g_cnt[i0] : 0;
    int e1 = (i1 < N) ? g_cnt[i1] : 0;
    int s = e0 + e1;
#pragma unroll
    for (int o = 16; o > 0; o >>= 1) s += __shfl_down_sync(0xffffffffu, s, o);
    if ((t & 31) == 0) wsum[t >> 5] = s;
    __syncthreads();
    if (t < 8) {
        int v = wsum[t];
#pragma unroll
        for (int o = 4; o > 0; o >>= 1) v += __shfl_down_sync(0xffu, v, o);
        if (t == 0) g_blocksum[b] = v;
    }
}

__global__ void k_scan2() {
    __shared__ int sh[128];
    const int t = threadIdx.x;
    int v = (t < NUM_SCAN_BLOCKS) ? g_blocksum[t] : 0;
    sh[t] = v;
    __syncthreads();
    for (int o = 1; o < 128; o <<= 1) {
        int u = (t >= o) ? sh[t - o] : 0;
        __syncthreads();
        sh[t] += u;
        __syncthreads();
    }
    if (t < NUM_SCAN_BLOCKS) g_blockbase[t] = sh[t] - v;  // exclusive
}

__global__ void k_scan3(int N) {
    __shared__ int warp_inc[8];
    const int b = blockIdx.x, t = threadIdx.x;
    const int lane = t & 31, wid = t >> 5;
    const int i0 = b * SCAN_CHUNK + 2 * t;
    const int i1 = i0 + 1;
    int e0 = (i0 < N) ? g_cnt[i0] : 0;
    int e1 = (i1 < N) ? g_cnt[i1] : 0;
    int s = e0 + e1;

    int v = s;
#pragma unroll
    for (int o = 1; o < 32; o <<= 1) {
        int u = __shfl_up_sync(0xffffffffu, v, o);
        if (lane >= o) v += u;
    }
    if (lane == 31) warp_inc[wid] = v;
    __syncthreads();
    if (t < 8) {
        int w = warp_inc[t];
#pragma unroll
        for (int o = 1; o < 8; o <<= 1) {
            int u = __shfl_up_sync(0xffu, w, o);
            if (t >= o) w += u;
        }
        warp_inc[t] = w;
    }
    __syncthreads();

    int base = g_blockbase[b] + (wid > 0 ? warp_inc[wid - 1] : 0) + (v - s);
    if (i0 < N) {
        g_start[i0]  = base;
        g_cursor[i0] = base;
        g_dinv[i0]   = rsqrtf((float)(e0 + 1));
        if (i0 == N - 1) g_start[N] = base + e0;
    }
    if (i1 < N) {
        int b1 = base + e0;
        g_start[i1]  = b1;
        g_cursor[i1] = b1;
        g_dinv[i1]   = rsqrtf((float)(e1 + 1));
        if (i1 == N - 1) g_start[N] = b1 + e1;
    }
}

// ---------------------------------------------------------------------------
__global__ void k_place(const int* __restrict__ p32, int E, int N) {
    int e = blockIdx.x * blockDim.x + threadIdx.x;
    if (e < E) {
        int stride = 1 + g_is64;
        int r = load_idx(p32, (long long)e, stride, N);
        int c = load_idx(p32, (long long)E + e, stride, N);
        int pos = atomicAdd(&g_cursor[c], 1);
        if (pos < MAXE) g_esrc[pos] = r;
    }
}

// ---------------------------------------------------------------------------
// k_gemm: h = x @ W via tf32 mma.sync m16n8k8, output stored as bf16.
// ---------------------------------------------------------------------------
#define BM 128
#define BN 64
#define BK 32

__device__ __forceinline__ unsigned f2tf32(float f) {
    unsigned r;
    asm("cvt.rna.tf32.f32 %0, %1;" : "=r"(r) : "f"(f));
    return r;
}

__device__ __forceinline__ void mma_tf32(float* d, const unsigned* a,
                                         const unsigned* b) {
    asm volatile(
        "mma.sync.aligned.m16n8k8.row.col.f32.tf32.tf32.f32 "
        "{%0,%1,%2,%3}, {%4,%5,%6,%7}, {%8,%9}, {%0,%1,%2,%3};"
        : "+f"(d[0]), "+f"(d[1]), "+f"(d[2]), "+f"(d[3])
        : "r"(a[0]), "r"(a[1]), "r"(a[2]), "r"(a[3]), "r"(b[0]), "r"(b[1]));
}

__global__ void k_gemm(const float* __restrict__ x,
                       const float* __restrict__ W, int N) {
    __shared__ float xs[BM][36];   // 128x32, row stride 36 (4g+t bijective)
    __shared__ float ws[BK][72];   // 32x64, row stride 72 (8t+g bijective)

    const int tid  = threadIdx.x;
    const int warp = tid >> 5;
    const int lane = tid & 31;
    const int g    = lane >> 2;
    const int t4   = lane & 3;

    const int rowBase = blockIdx.x * BM;
    const int colBase = blockIdx.y * BN;
    const int wm = (warp >> 1) * 32;
    const int wn = (warp & 1) * 32;

    float acc[2][4][4];
#pragma unroll
    for (int m = 0; m < 2; m++)
#pragma unroll
        for (int n = 0; n < 4; n++)
#pragma unroll
            for (int r = 0; r < 4; r++) acc[m][n][r] = 0.0f;

    for (int kc = 0; kc < DIM; kc += BK) {
#pragma unroll
        for (int l = 0; l < 4; l++) {
            int idx = tid + l * 256;
            int r = idx >> 3, c4 = idx & 7;
            int gr = rowBase + r;
            float4 v = (gr < N)
                ? *(const float4*)&x[(size_t)gr * DIM + kc + c4 * 4]
                : make_float4(0.f, 0.f, 0.f, 0.f);
            *(float4*)&xs[r][c4 * 4] = v;
        }
#pragma unroll
        for (int l = 0; l < 2; l++) {
            int idx = tid + l * 256;
            int r = idx >> 4, c4 = idx & 15;
            float4 v = *(const float4*)&W[(size_t)(kc + r) * DIM + colBase + c4 * 4];
            *(float4*)&ws[r][c4 * 4] = v;
        }
        __syncthreads();

#pragma unroll
        for (int ks = 0; ks < BK; ks += 8) {
            unsigned A[2][4], B[4][2];
#pragma unroll
            for (int m = 0; m < 2; m++) {
                int r0 = wm + m * 16 + g;
                A[m][0] = f2tf32(xs[r0][ks + t4]);
                A[m][1] = f2tf32(xs[r0 + 8][ks + t4]);
                A[m][2] = f2tf32(xs[r0][ks + t4 + 4]);
                A[m][3] = f2tf32(xs[r0 + 8][ks + t4 + 4]);
            }
#pragma unroll
            for (int n = 0; n < 4; n++) {
                int c = wn + n * 8 + g;
                B[n][0] = f2tf32(ws[ks + t4][c]);
                B[n][1] = f2tf32(ws[ks + t4 + 4][c]);
            }
#pragma unroll
            for (int m = 0; m < 2; m++)
#pragma unroll
                for (int n = 0; n < 4; n++) mma_tf32(acc[m][n], A[m], B[n]);
        }
        __syncthreads();
    }

    // store as bf16
#pragma unroll
    for (int m = 0; m < 2; m++) {
        int r0 = rowBase + wm + m * 16 + g;
        int r1 = r0 + 8;
#pragma unroll
        for (int n = 0; n < 4; n++) {
            int c = colBase + wn + n * 8 + 2 * t4;
            if (r0 < N)
                *(__nv_bfloat162*)&g_hb[(size_t)r0 * DIM + c] =
                    __floats2bfloat162_rn(acc[m][n][0], acc[m][n][1]);
            if (r1 < N)
                *(__nv_bfloat162*)&g_hb[(size_t)r1 * DIM + c] =
                    __floats2bfloat162_rn(acc[m][n][2], acc[m][n][3]);
        }
    }
}

// ---------------------------------------------------------------------------
// k_gather: fused aggregate + bias + sigmoid + column-sum. Warp per node.
// bf16 h, edge loop 4x unrolled: 4 independent uint4 loads in flight per
// lane (restores fp32-era MLP=4 at half the bytes).
// ---------------------------------------------------------------------------
#define GATHER_BLOCKS 1184
__device__ __forceinline__ float sigmoidf(float v) {
    return 1.0f / (1.0f + expf(-v));
}

__device__ __forceinline__ void unpack8(const uint4& u, float* f) {
    float2 p;
    p = __bfloat1622float2(*(const __nv_bfloat162*)&u.x); f[0] = p.x; f[1] = p.y;
    p = __bfloat1622float2(*(const __nv_bfloat162*)&u.y); f[2] = p.x; f[3] = p.y;
    p = __bfloat1622float2(*(const __nv_bfloat162*)&u.z); f[4] = p.x; f[5] = p.y;
    p = __bfloat1622float2(*(const __nv_bfloat162*)&u.w); f[6] = p.x; f[7] = p.y;
}

__global__ void k_gather(const float* __restrict__ b_conv, int N) {
    const int lane = threadIdx.x & 31;
    const int wid  = threadIdx.x >> 5;
    const int gw   = blockIdx.x * 8 + wid;
    const int nwarps = gridDim.x * 8;
    const int d0 = lane * 8;

    const uint4* __restrict__ hb4 = (const uint4*)g_hb;
    const int rowStride = DIM / 8;       // 32 uint4 per row
    const int laneOff = lane;

    float bc[8];
#pragma unroll
    for (int j = 0; j < 8; j++) bc[j] = b_conv[d0 + j];

    float cs[8];
#pragma unroll
    for (int j = 0; j < 8; j++) cs[j] = 0.0f;

    for (int n = gw; n < N; n += nwarps) {
        const float dn = g_dinv[n];
        const int base = g_start[n];
        const int end  = g_start[n + 1];

        float a[8];
        {   // self-loop: norm = dinv[n]^2
            const float wn = dn * dn;
            float hv[8];
            unpack8(hb4[(size_t)n * rowStride + laneOff], hv);
#pragma unroll
            for (int j = 0; j < 8; j++) a[j] = hv[j] * wn;
        }

        int i = base;
        // 4x unrolled: 4 indices, then 4 independent LDG.128 in flight
        for (; i + 4 <= end; i += 4) {
            int r0 = g_esrc[i];
            int r1 = g_esrc[i + 1];
            int r2 = g_esrc[i + 2];
            int r3 = g_esrc[i + 3];
            float w0 = g_dinv[r0] * dn;
            float w1 = g_dinv[r1] * dn;
            float w2 = g_dinv[r2] * dn;
            float w3 = g_dinv[r3] * dn;
            uint4 u0 = hb4[(size_t)r0 * rowStride + laneOff];
            uint4 u1 = hb4[(size_t)r1 * rowStride + laneOff];
            uint4 u2 = hb4[(size_t)r2 * rowStride + laneOff];
            uint4 u3 = hb4[(size_t)r3 * rowStride + laneOff];
            float v0[8], v1[8], v2[8], v3[8];
            unpack8(u0, v0);
            unpack8(u1, v1);
            unpack8(u2, v2);
            unpack8(u3, v3);
#pragma unroll
            for (int j = 0; j < 8; j++) a[j] = fmaf(v0[j], w0, a[j]);
#pragma unroll
            for (int j = 0; j < 8; j++) a[j] = fmaf(v1[j], w1, a[j]);
#pragma unroll
            for (int j = 0; j < 8; j++) a[j] = fmaf(v2[j], w2, a[j]);
#pragma unroll
            for (int j = 0; j < 8; j++) a[j] = fmaf(v3[j], w3, a[j]);
        }
        for (; i < end; i++) {
            int   r  = g_esrc[i];
            float we = g_dinv[r] * dn;
            float v[8];
            unpack8(hb4[(size_t)r * rowStride + laneOff], v);
#pragma unroll
            for (int j = 0; j < 8; j++) a[j] = fmaf(v[j], we, a[j]);
        }

#pragma unroll
        for (int j = 0; j < 8; j++) cs[j] += sigmoidf(a[j] + bc[j]);
    }

    __shared__ float scol[DIM];
    scol[threadIdx.x] = 0.0f;
    __syncthreads();
#pragma unroll
    for (int j = 0; j < 8; j++) atomicAdd(&scol[d0 + j], cs[j]);
    __syncthreads();
    atomicAdd(&g_colsum[threadIdx.x], scol[threadIdx.x]);
}

// ---------------------------------------------------------------------------
__global__ void k_final(const float* __restrict__ w_lin,
                        const float* __restrict__ b_lin,
                        float* __restrict__ out, int N) {
    __shared__ float red[DIM];
    int d = threadIdx.x;
    red[d] = g_colsum[d] * (1.0f / (float)N) * w_lin[d];
    __syncthreads();
    for (int s = 128; s > 0; s >>= 1) {
        if (d < s) red[d] += red[d + s];
        __syncthreads();
    }
    if (d == 0) {
        float z = red[0] + b_lin[0];
        out[0] = 1.0f / (1.0f + expf(-z));
    }
}

// ---------------------------------------------------------------------------
extern "C" void kernel_launch(void* const* d_in, const int* in_sizes, int n_in,
                              void* d_out, int out_size) {
    const float* x      = (const float*)d_in[0];
    const int*   e32    = (const int*)d_in[1];
    const float* W      = (const float*)d_in[2];
    const float* b_conv = (const float*)d_in[3];
    const float* w_lin  = (const float*)d_in[4];
    const float* b_lin  = (const float*)d_in[5];
    float*       out    = (float*)d_out;

    int N = in_sizes[0] / DIM;
    int E = in_sizes[1] / 2;

    k_detect<<<1, 256>>>(e32, 2 * E);
    k_init<<<(N + 255) / 256, 256>>>(N);
    k_hist<<<(E + 255) / 256, 256>>>(e32, E, N);

    k_scan1<<<NUM_SCAN_BLOCKS, 256>>>(N);
    k_scan2<<<1, 128>>>();
    k_scan3<<<NUM_SCAN_BLOCKS, 256>>>(N);

    k_place<<<(E + 255) / 256, 256>>>(e32, E, N);
    {
        dim3 grid((N + BM - 1) / BM, DIM / BN);
        k_gemm<<<grid, 256>>>(x, W, N);
    }
    k_gather<<<GATHER_BLOCKS, 256>>>(b_conv, N);
    k_final<<<1, 256>>>(w_lin, b_lin, out, N);
}